// round 8
// baseline (speedup 1.0000x reference)
#include <cuda_runtime.h>
#include <cstdint>

// Problem constants (fixed shapes)
#define T_DIM 64
#define U_DIM 142
#define I_DIM 4500
#define K_TOP 10
#define ROWS_PER_WARP 2

#define KEY_ZERO 0x80000000u   // order-key of +0.0f

// monotone float -> u32 order key (increasing)
__device__ __forceinline__ unsigned fkey(float f) {
    unsigned u = __float_as_uint(f);
    return u ^ ((unsigned)((int)u >> 31) | 0x80000000u);
}

// REDUX-based top-K weighted accumulate for one row.
// Inputs: c (qos col values, lane-private), sim row base, avg row base.
// Returns corr = sum(top_sim * d) / (sum(top_sim)+eps)  (valid on all lanes' lane0 sum).
__device__ __forceinline__ float topk_corr(
    float c0, float c1, float c2, float c3, float c4,
    const float* __restrict__ sbase, const float* __restrict__ abase,
    int lane, bool tail)
{
    const int v0 = lane, v1 = lane + 32, v2 = lane + 64, v3 = lane + 96, v4 = lane + 128;

    float s0 = __ldg(sbase + v0), a0 = __ldg(abase + v0);
    float s1 = __ldg(sbase + v1), a1 = __ldg(abase + v1);
    float s2 = __ldg(sbase + v2), a2 = __ldg(abase + v2);
    float s3 = __ldg(sbase + v3), a3 = __ldg(abase + v3);
    float s4 = tail ? __ldg(sbase + v4) : 0.f;
    float a4 = tail ? __ldg(abase + v4) : 0.f;

    unsigned k0 = fkey((c0 > 0.f) ? s0 : 0.f);
    unsigned k1 = fkey((c1 > 0.f) ? s1 : 0.f);
    unsigned k2 = fkey((c2 > 0.f) ? s2 : 0.f);
    unsigned k3 = fkey((c3 > 0.f) ? s3 : 0.f);
    unsigned k4 = tail ? fkey((c4 > 0.f) ? s4 : 0.f) : 0u;
    float d0 = c0 - a0, d1 = c1 - a1, d2 = c2 - a2, d3 = c3 - a3, d4 = c4 - a4;

    float wsum = 0.f, acc = 0.f;
    #pragma unroll
    for (int k = 0; k < K_TOP; ++k) {
        unsigned lmax = max(max(max(k0, k1), max(k2, k3)), k4);
        unsigned g = __reduce_max_sync(0xffffffffu, lmax);   // REDUX.MAX.U32
        if (g <= KEY_ZERO) break;  // remaining candidates are zeros: contribute 0
        float gm = __uint_as_float(g ^ 0x80000000u);         // winner sim (positive branch)
        wsum += gm;                                          // warp-uniform
        if      (k0 == g) { acc = fmaf(gm, d0, acc); k0 = 0u; }
        else if (k1 == g) { acc = fmaf(gm, d1, acc); k1 = 0u; }
        else if (k2 == g) { acc = fmaf(gm, d2, acc); k2 = 0u; }
        else if (k3 == g) { acc = fmaf(gm, d3, acc); k3 = 0u; }
        else if (k4 == g) { acc = fmaf(gm, d4, acc); k4 = 0u; }
    }

    #pragma unroll
    for (int off = 16; off > 0; off >>= 1)
        acc += __shfl_xor_sync(0xffffffffu, acc, off);

    return acc / (wsum + 1e-8f);
}

__global__ __launch_bounds__(256)
void ucf_kernel(const float* __restrict__ qos,        // [T, U, I]
                const float* __restrict__ user_avg,   // [T, U]
                const float* __restrict__ user_sim,   // [U, U]
                const int*   __restrict__ user_id,    // [B]
                const int*   __restrict__ item_id,    // [B]
                const int*   __restrict__ time_id,    // [B]
                float*       __restrict__ out,        // [B]
                int B)
{
    const int warp = (blockIdx.x * blockDim.x + threadIdx.x) >> 5;
    const int lane = threadIdx.x & 31;

    const int r0 = warp * ROWS_PER_WARP;
    const int r1 = r0 + 1;
    if (r0 >= B) return;
    const bool have1 = (r1 < B);

    const int u0 = user_id[r0], i0 = item_id[r0], t0 = time_id[r0];
    const int u1 = have1 ? user_id[r1] : u0;
    const int i1 = have1 ? item_id[r1] : i0;
    const int t1 = have1 ? time_id[r1] : t0;

    const float* qb0 = qos + (int64_t)t0 * (U_DIM * I_DIM) + i0;
    const float* qb1 = qos + (int64_t)t1 * (U_DIM * I_DIM) + i1;

    const int v0 = lane, v1 = lane + 32, v2 = lane + 64, v3 = lane + 96;
    const int v4 = lane + 128;
    const bool tail = (v4 < U_DIM);

    // ---- front-batch ALL scattered qos loads (both rows): MLP = 10 ----
    float c00 = __ldg(qb0 + (int64_t)v0 * I_DIM);
    float c01 = __ldg(qb0 + (int64_t)v1 * I_DIM);
    float c02 = __ldg(qb0 + (int64_t)v2 * I_DIM);
    float c03 = __ldg(qb0 + (int64_t)v3 * I_DIM);
    float c04 = tail ? __ldg(qb0 + (int64_t)v4 * I_DIM) : 0.f;

    float c10 = __ldg(qb1 + (int64_t)v0 * I_DIM);
    float c11 = __ldg(qb1 + (int64_t)v1 * I_DIM);
    float c12 = __ldg(qb1 + (int64_t)v2 * I_DIM);
    float c13 = __ldg(qb1 + (int64_t)v3 * I_DIM);
    float c14 = tail ? __ldg(qb1 + (int64_t)v4 * I_DIM) : 0.f;

    // ---- row 0 selection (row 1 loads remain in flight) ----
    {
        const float* ab0 = user_avg + t0 * U_DIM;
        float corr = topk_corr(c00, c01, c02, c03, c04,
                               user_sim + u0 * U_DIM, ab0, lane, tail);
        if (lane == 0) out[r0] = __ldg(ab0 + u0) + corr;
    }

    // ---- row 1 selection ----
    if (have1) {
        const float* ab1 = user_avg + t1 * U_DIM;
        float corr = topk_corr(c10, c11, c12, c13, c14,
                               user_sim + u1 * U_DIM, ab1, lane, tail);
        if (lane == 0) out[r1] = __ldg(ab1 + u1) + corr;
    }
}

extern "C" void kernel_launch(void* const* d_in, const int* in_sizes, int n_in,
                              void* d_out, int out_size)
{
    const float* qos      = (const float*)d_in[0];
    const float* user_avg = (const float*)d_in[1];
    const float* user_sim = (const float*)d_in[2];
    const int*   user_id  = (const int*)  d_in[3];
    const int*   item_id  = (const int*)  d_in[4];
    const int*   time_id  = (const int*)  d_in[5];
    float* out = (float*)d_out;

    const int B = in_sizes[3];
    const int threads = 256;                                    // 8 warps/block
    const int rows_per_block = (threads / 32) * ROWS_PER_WARP;  // 16
    const int blocks = (B + rows_per_block - 1) / rows_per_block;
    ucf_kernel<<<blocks, threads>>>(qos, user_avg, user_sim,
                                    user_id, item_id, time_id, out, B);
}